// round 2
// baseline (speedup 1.0000x reference)
#include <cuda_runtime.h>
#include <math.h>

#define C 128
#define NE_MAX 800000
#define NN_MAX 50000
#define BN_EPS 1e-5f

typedef unsigned long long u64;

// ---------------- scratch (device globals; no runtime alloc allowed) ----------------
__device__ float g_h[(size_t)NE_MAX * C];     // edge MLP pre-BN output (409.6 MB)
__device__ float g_xa[(size_t)NN_MAX * C];    // x @ w1a^T
__device__ float g_agg[(size_t)NN_MAX * C];   // scatter sum
__device__ float g_pre[(size_t)NN_MAX * C];   // node MLP pre-BN output
__device__ float g_w1at[C * C];               // [k][j] = w1[j][k]
__device__ float g_w1bt[C * C];               // [k][j] = w1[j][k+C]
__device__ float g_w2t[2 * C * C];            // [k][j] = w2[j][k]
__device__ float g_cnt[NN_MAX];
__device__ float g_s1[C], g_q1[C], g_s2[C], g_q2[C];
__device__ float g_a1[C], g_c1[C], g_a2[C], g_c2[C];

// ---------------- f32x2 packed math helpers ----------------
__device__ __forceinline__ u64 dupf(float v) {
    u64 d; asm("mov.b64 %0, {%1, %1};" : "=l"(d) : "f"(v)); return d;
}
__device__ __forceinline__ void ffma2(u64& d, u64 a, u64 b) {
    asm("fma.rn.f32x2 %0, %1, %2, %0;" : "+l"(d) : "l"(a), "l"(b));
}
__device__ __forceinline__ float f2lo(u64 v) { return __uint_as_float((unsigned)v); }
__device__ __forceinline__ float f2hi(u64 v) { return __uint_as_float((unsigned)(v >> 32)); }

__device__ __forceinline__ float eluf(float v) { return v > 0.f ? v : expm1f(v); }

// vectorized global float4 reduction (sm_90+)
__device__ __forceinline__ void red4(float* p, float a, float b, float c, float d) {
    asm volatile("red.global.add.v4.f32 [%0], {%1,%2,%3,%4};"
                 :: "l"(p), "f"(a), "f"(b), "f"(c), "f"(d) : "memory");
}

// ---------------- misc small kernels ----------------
__global__ void zero_kernel() {
    int g = blockIdx.x * 256 + threadIdx.x;
    if (g < NN_MAX * C / 4) ((float4*)g_agg)[g] = make_float4(0.f, 0.f, 0.f, 0.f);
    if (g < NN_MAX) g_cnt[g] = 0.f;
    if (g < C) { g_s1[g] = 0.f; g_q1[g] = 0.f; g_s2[g] = 0.f; g_q2[g] = 0.f; }
}

__global__ void prep_w(const float* __restrict__ w1, const float* __restrict__ w2) {
    int k = blockIdx.x;     // 0..255
    int j = threadIdx.x;    // 0..127
    if (k < C) {
        g_w1at[k * C + j] = w1[j * 2 * C + k];
        g_w1bt[k * C + j] = w1[j * 2 * C + C + k];
    }
    g_w2t[k * C + j] = w2[j * 2 * C + k];
}

__global__ void count_kernel(const int* __restrict__ col, int E) {
    int e = blockIdx.x * 256 + threadIdx.x;
    if (e < E) atomicAdd(&g_cnt[col[e]], 1.f);
}

// ---------------- GEMM: out[m][j] = sum_k A[m][k] * Bt[k][j] (+ epilogue) ----------------
// MODE 0: A=x (M x 128), Bt=g_w1at, Out=g_xa, no bias, no stats
// MODE 1: A=edge_attr (M x 128), Bt=g_w1bt, Out=g_h, epilogue += g_xa[row[m]] + b1, stats->s1/q1
// MODE 2: A=concat(x, g_agg/cnt) (M x 256), Bt=g_w2t, Out=g_pre, epilogue += b2, stats->s2/q2
//
// smem: B resident for the whole block (duplicated f32x2 pairs for MODE 0/1,
// plain floats for MODE 2), A double-buffered in BK=32 chunks with
// register-staged prefetch. One __syncthreads per chunk.
template <int MODE, int KD>
__global__ void __launch_bounds__(256) gemm_kernel(
    const float* __restrict__ A, const float* __restrict__ bias,
    const int* __restrict__ rowidx, int M)
{
    constexpr int AS = 132;
    constexpr int NC = KD / 32;
    extern __shared__ char smraw[];
    u64*   Bd  = (u64*)smraw;                                     // MODE 0/1: [KD][C] duplicated
    float* Bs  = (float*)smraw;                                   // MODE 2:  [KD][C]
    float* Asm = (MODE == 2) ? (float*)(smraw + (size_t)KD * C * 4)
                             : (float*)(smraw + (size_t)KD * C * 8);

    const float* Bt = (MODE == 0) ? g_w1at : (MODE == 1) ? g_w1bt : g_w2t;
    float* Out = (MODE == 0) ? g_xa : (MODE == 1) ? g_h : g_pre;
    float* Sg = (MODE == 1) ? g_s1 : g_s2;
    float* Qg = (MODE == 1) ? g_q1 : g_q2;

    const int tid = threadIdx.x;
    const int mbase = blockIdx.x * 128;

    // ---- load B (once) ----
    if (MODE == 2) {
        for (int i = tid * 4; i < KD * C; i += 1024)
            *(float4*)(Bs + i) = *(const float4*)(Bt + i);
    } else {
        for (int i = tid * 4; i < KD * C; i += 1024) {
            float4 v = *(const float4*)(Bt + i);
            ulonglong2 p0 = {dupf(v.x), dupf(v.y)};
            ulonglong2 p1 = {dupf(v.z), dupf(v.w)};
            *(ulonglong2*)(Bd + i)     = p0;
            *(ulonglong2*)(Bd + i + 2) = p1;
        }
    }

    // ---- A staging helpers ----
    const int skq = tid & 7;        // float4 slot within a BK=32 chunk
    const int sm0 = tid >> 3;       // base m-line (stride 32 over i)

    auto ldA = [&](int k0, float4* dst) {
#pragma unroll
        for (int i = 0; i < 4; i++) {
            int m = mbase + sm0 + i * 32; if (m >= M) m = M - 1;
            int k = k0 + skq * 4;
            if (MODE == 2) {
                if (k < C) {
                    dst[i] = *(const float4*)(A + (size_t)m * C + k);
                } else {
                    float4 v = *(const float4*)(g_agg + (size_t)m * C + (k - C));
                    float s = __frcp_rn(fmaxf(g_cnt[m], 1.f));
                    v.x *= s; v.y *= s; v.z *= s; v.w *= s;
                    dst[i] = v;
                }
            } else {
                dst[i] = *(const float4*)(A + (size_t)m * KD + k);
            }
        }
    };
    auto stA = [&](int buf, const float4* src) {
        float* As = Asm + buf * (32 * AS);
#pragma unroll
        for (int i = 0; i < 4; i++) {
            int ml = sm0 + i * 32;
            As[(skq * 4 + 0) * AS + ml] = src[i].x;
            As[(skq * 4 + 1) * AS + ml] = src[i].y;
            As[(skq * 4 + 2) * AS + ml] = src[i].z;
            As[(skq * 4 + 3) * AS + ml] = src[i].w;
        }
    };

    // ---- pipeline prologue ----
    float4 cur[4], nxt[4];
    ldA(0, cur);
    if (NC > 1) ldA(32, nxt);
    stA(0, cur);
    __syncthreads();

    // ---- microtile setup ----
    const int tx = tid & 15, ty = tid >> 4;
    const int m0 = tx * 8, n0 = ty * 8;

    u64 acc[4][8];
#pragma unroll
    for (int i = 0; i < 4; i++)
#pragma unroll
        for (int j = 0; j < 8; j++) acc[i][j] = 0ull;

    // ---- mainloop ----
    for (int ck = 0; ck < NC; ck++) {
        if (ck + 1 < NC) stA((ck + 1) & 1, nxt);
        if (ck + 2 < NC) ldA((ck + 2) * 32, nxt);

        const float* As = Asm + (ck & 1) * (32 * AS);
#pragma unroll
        for (int k = 0; k < 32; k++) {
            const int kk = ck * 32 + k;
            ulonglong2 av0 = *(const ulonglong2*)(As + k * AS + m0);
            ulonglong2 av1 = *(const ulonglong2*)(As + k * AS + m0 + 4);
            u64 a0 = av0.x, a1 = av0.y, a2 = av1.x, a3 = av1.y;
            if (MODE != 2) {
                const u64* bp = Bd + (size_t)kk * C + n0;
#pragma unroll
                for (int nn = 0; nn < 8; nn += 2) {
                    ulonglong2 bv = *(const ulonglong2*)(bp + nn);
                    ffma2(acc[0][nn], a0, bv.x);
                    ffma2(acc[1][nn], a1, bv.x);
                    ffma2(acc[2][nn], a2, bv.x);
                    ffma2(acc[3][nn], a3, bv.x);
                    ffma2(acc[0][nn + 1], a0, bv.y);
                    ffma2(acc[1][nn + 1], a1, bv.y);
                    ffma2(acc[2][nn + 1], a2, bv.y);
                    ffma2(acc[3][nn + 1], a3, bv.y);
                }
            } else {
                float4 b0 = *(const float4*)(Bs + (size_t)kk * C + n0);
                float4 b1 = *(const float4*)(Bs + (size_t)kk * C + n0 + 4);
                float bb[8] = {b0.x, b0.y, b0.z, b0.w, b1.x, b1.y, b1.z, b1.w};
#pragma unroll
                for (int nn = 0; nn < 8; nn++) {
                    u64 bd = dupf(bb[nn]);
                    ffma2(acc[0][nn], a0, bd);
                    ffma2(acc[1][nn], a1, bd);
                    ffma2(acc[2][nn], a2, bd);
                    ffma2(acc[3][nn], a3, bd);
                }
            }
        }
        if (ck + 1 < NC) __syncthreads();
    }

    // ---- epilogue: bias / xa-gather, store, fused BN stats ----
    float4 bi0, bi1;
    if (MODE != 0) {
        bi0 = *(const float4*)(bias + n0);
        bi1 = *(const float4*)(bias + n0 + 4);
    }
    float s8[8], q8[8];
#pragma unroll
    for (int nn = 0; nn < 8; nn++) { s8[nn] = 0.f; q8[nn] = 0.f; }

#pragma unroll
    for (int mp = 0; mp < 4; mp++) {
#pragma unroll
        for (int h = 0; h < 2; h++) {
            int m = mbase + m0 + mp * 2 + h;
            if (m >= M) continue;
            float o[8];
#pragma unroll
            for (int nn = 0; nn < 8; nn++) o[nn] = h ? f2hi(acc[mp][nn]) : f2lo(acc[mp][nn]);
            if (MODE == 1) {
                int r = rowidx[m];
                const float4* xr = (const float4*)(g_xa + (size_t)r * C + n0);
                float4 x0 = xr[0], x1 = xr[1];
                o[0] += x0.x + bi0.x; o[1] += x0.y + bi0.y;
                o[2] += x0.z + bi0.z; o[3] += x0.w + bi0.w;
                o[4] += x1.x + bi1.x; o[5] += x1.y + bi1.y;
                o[6] += x1.z + bi1.z; o[7] += x1.w + bi1.w;
            } else if (MODE == 2) {
                o[0] += bi0.x; o[1] += bi0.y; o[2] += bi0.z; o[3] += bi0.w;
                o[4] += bi1.x; o[5] += bi1.y; o[6] += bi1.z; o[7] += bi1.w;
            }
            if (MODE != 0) {
#pragma unroll
                for (int nn = 0; nn < 8; nn++) { s8[nn] += o[nn]; q8[nn] += o[nn] * o[nn]; }
            }
            float4 w0 = {o[0], o[1], o[2], o[3]};
            float4 w1v = {o[4], o[5], o[6], o[7]};
            *(float4*)(Out + (size_t)m * C + n0) = w0;
            *(float4*)(Out + (size_t)m * C + n0 + 4) = w1v;
        }
    }

    if (MODE != 0) {
        // half-warp (16 lanes share the same channel group n0) reduction
#pragma unroll
        for (int off = 8; off; off >>= 1) {
#pragma unroll
            for (int nn = 0; nn < 8; nn++) {
                s8[nn] += __shfl_down_sync(0xffffffffu, s8[nn], off, 16);
                q8[nn] += __shfl_down_sync(0xffffffffu, q8[nn], off, 16);
            }
        }
        if ((tid & 15) == 0) {
            red4(Sg + n0,     s8[0], s8[1], s8[2], s8[3]);
            red4(Sg + n0 + 4, s8[4], s8[5], s8[6], s8[7]);
            red4(Qg + n0,     q8[0], q8[1], q8[2], q8[3]);
            red4(Qg + n0 + 4, q8[4], q8[5], q8[6], q8[7]);
        }
    }
}

// ---------------- BN coefficient finalize ----------------
__global__ void finalize_kernel(int sel, const float* __restrict__ bnw,
                                const float* __restrict__ bnb, float minv) {
    int j = threadIdx.x;
    float s  = sel ? g_s2[j] : g_s1[j];
    float q  = sel ? g_q2[j] : g_q1[j];
    float mu = s * minv;
    float var = q * minv - mu * mu;
    float r = rsqrtf(var + BN_EPS);
    float a = r * bnw[j];
    float c = bnb[j] - mu * a;
    if (sel) { g_a2[j] = a; g_c2[j] = c; }
    else     { g_a1[j] = a; g_c1[j] = c; }
}

// ---------------- BN1 + ELU + vectorized scatter-add into g_agg ----------------
__global__ void scatter_kernel(const int* __restrict__ col, int E) {
    int g = blockIdx.x * 256 + threadIdx.x;
    if (g >= E * 32) return;
    int e = g >> 5;                 // whole warp shares one edge -> broadcast load
    int cq = (g & 31) * 4;
    float4 v = *(const float4*)(g_h + (size_t)g * 4);
    float4 a = *(const float4*)(g_a1 + cq);
    float4 c = *(const float4*)(g_c1 + cq);
    int d = col[e];
    float* base = g_agg + (size_t)d * C + cq;
    red4(base,
         eluf(fmaf(v.x, a.x, c.x)),
         eluf(fmaf(v.y, a.y, c.y)),
         eluf(fmaf(v.z, a.z, c.z)),
         eluf(fmaf(v.w, a.w, c.w)));
}

// ---------------- BN2 + ELU -> output ----------------
__global__ void final_kernel(float* __restrict__ out, int n) {
    int g = blockIdx.x * 256 + threadIdx.x;
    if (g >= n * 32) return;
    int cq = (g & 31) * 4;
    float4 v = *(const float4*)(g_pre + (size_t)g * 4);
    float4 a = *(const float4*)(g_a2 + cq);
    float4 c = *(const float4*)(g_c2 + cq);
    float4 o;
    o.x = eluf(fmaf(v.x, a.x, c.x));
    o.y = eluf(fmaf(v.y, a.y, c.y));
    o.z = eluf(fmaf(v.z, a.z, c.z));
    o.w = eluf(fmaf(v.w, a.w, c.w));
    *(float4*)(out + (size_t)g * 4) = o;
}

// ---------------- launch ----------------
extern "C" void kernel_launch(void* const* d_in, const int* in_sizes, int n_in,
                              void* d_out, int out_size) {
    const float* x    = (const float*)d_in[0];
    const int*   ei   = (const int*)d_in[1];
    const float* ea   = (const float*)d_in[2];
    // d_in[3] = u (unused), d_in[4] = batch (unused)
    const float* w1   = (const float*)d_in[5];
    const float* b1   = (const float*)d_in[6];
    const float* bn1w = (const float*)d_in[7];
    const float* bn1b = (const float*)d_in[8];
    const float* w2   = (const float*)d_in[9];
    const float* b2   = (const float*)d_in[10];
    const float* bn2w = (const float*)d_in[11];
    const float* bn2b = (const float*)d_in[12];
    float* out = (float*)d_out;

    int n = in_sizes[0] / C;           // 50000
    int E = in_sizes[2] / C;           // 800000
    const int* row = ei;
    const int* col = ei + E;

    // dynamic smem: B resident (131072 B) + double-buffered A (33792 B)
    const int SMEM_GEMM = 131072 + 2 * 32 * 132 * 4;
    cudaFuncSetAttribute(gemm_kernel<0, 128>, cudaFuncAttributeMaxDynamicSharedMemorySize, SMEM_GEMM);
    cudaFuncSetAttribute(gemm_kernel<1, 128>, cudaFuncAttributeMaxDynamicSharedMemorySize, SMEM_GEMM);
    cudaFuncSetAttribute(gemm_kernel<2, 256>, cudaFuncAttributeMaxDynamicSharedMemorySize, SMEM_GEMM);

    zero_kernel<<<(NN_MAX * C / 4 + 255) / 256, 256>>>();
    prep_w<<<2 * C, C>>>(w1, w2);
    count_kernel<<<(E + 255) / 256, 256>>>(col, E);

    // xa = x @ w1a^T
    gemm_kernel<0, 128><<<(n + 127) / 128, 256, SMEM_GEMM>>>(x, nullptr, nullptr, n);
    // h = ea @ w1b^T + xa[row] + b1   (stats fused)
    gemm_kernel<1, 128><<<(E + 127) / 128, 256, SMEM_GEMM>>>(ea, b1, row, E);
    finalize_kernel<<<1, C>>>(0, bn1w, bn1b, 1.f / (float)E);

    scatter_kernel<<<(E * 32 + 255) / 256, 256>>>(col, E);

    // pre = [x, agg/cnt] @ w2^T + b2   (stats fused)
    gemm_kernel<2, 256><<<(n + 127) / 128, 256, SMEM_GEMM>>>(x, b2, nullptr, n);
    finalize_kernel<<<1, C>>>(1, bn2w, bn2b, 1.f / (float)n);

    final_kernel<<<(n * 32 + 255) / 256, 256>>>(out, n);
}

// round 4
// speedup vs baseline: 1.3535x; 1.3535x over previous
#include <cuda_runtime.h>
#include <cuda_bf16.h>
#include <math.h>
#include <stdint.h>

#define C 128
#define NE_MAX 800000
#define NN_MAX 50000
#define BN_EPS 1e-5f

// ---------------- scratch (device globals; no runtime alloc) ----------------
__device__ float g_h[(size_t)NE_MAX * C];     // edge MLP pre-BN output
__device__ float g_xa[(size_t)NN_MAX * C];    // x @ w1a^T
__device__ float g_agg[(size_t)NN_MAX * C];   // scatter sum
__device__ float g_pre[(size_t)NN_MAX * C];   // node MLP pre-BN output
__device__ float g_cnt[NN_MAX];
__device__ float g_s1[C], g_q1[C], g_s2[C], g_q2[C];
__device__ float g_a1[C], g_c1[C], g_a2[C], g_c2[C];
// bf16 weight blobs in smem-swizzled [n][k] layout:
// 0,1 = w1a hi/lo ; 2,3 = w1b hi/lo ; 4,5 = w2a hi/lo ; 6,7 = w2b hi/lo
__device__ __align__(16) uint16_t g_wblob[8][128 * 128];

// ---------------- helpers ----------------
__device__ __forceinline__ uint32_t smem_u32(const void* p) {
    return (uint32_t)__cvta_generic_to_shared(p);
}
__device__ __forceinline__ void ldsm4(uint32_t* r, uint32_t addr) {
    asm volatile("ldmatrix.sync.aligned.m8n8.x4.shared.b16 {%0,%1,%2,%3}, [%4];"
                 : "=r"(r[0]), "=r"(r[1]), "=r"(r[2]), "=r"(r[3]) : "r"(addr));
}
__device__ __forceinline__ void mma16816(float* c, const uint32_t* a, const uint32_t* b) {
    asm volatile(
        "mma.sync.aligned.m16n8k16.row.col.f32.bf16.bf16.f32 "
        "{%0,%1,%2,%3}, {%4,%5,%6,%7}, {%8,%9}, {%0,%1,%2,%3};"
        : "+f"(c[0]), "+f"(c[1]), "+f"(c[2]), "+f"(c[3])
        : "r"(a[0]), "r"(a[1]), "r"(a[2]), "r"(a[3]), "r"(b[0]), "r"(b[1]));
}
__device__ __forceinline__ unsigned pack_bf16(float lo, float hi) {
    __nv_bfloat162 p = __floats2bfloat162_rn(lo, hi);
    return *reinterpret_cast<unsigned*>(&p);
}
__device__ __forceinline__ float eluf(float v) { return v > 0.f ? v : expm1f(v); }
__device__ __forceinline__ void red4(float* p, float a, float b, float c, float d) {
    asm volatile("red.global.add.v4.f32 [%0], {%1,%2,%3,%4};"
                 :: "l"(p), "f"(a), "f"(b), "f"(c), "f"(d) : "memory");
}
// swizzled byte offset for (row, 16B k-group) within a 128x128 bf16 tile
__device__ __forceinline__ uint32_t swz(int row, int kg) {
    return ((uint32_t)row << 8) + (((uint32_t)(kg ^ (row & 7))) << 4);
}

// ---------------- small kernels ----------------
__global__ void zero_kernel() {
    int g = blockIdx.x * 256 + threadIdx.x;
    if (g < NN_MAX * C / 4) ((float4*)g_agg)[g] = make_float4(0.f, 0.f, 0.f, 0.f);
    if (g < NN_MAX) g_cnt[g] = 0.f;
    if (g < C) { g_s1[g] = 0.f; g_q1[g] = 0.f; g_s2[g] = 0.f; g_q2[g] = 0.f; }
}

// split w1/w2 into hi/lo bf16 blobs, swizzled [n][k]
__global__ void prep_w(const float* __restrict__ w1, const float* __restrict__ w2) {
    int t = blockIdx.x * 256 + threadIdx.x;   // 0..2047
    if (t >= 2048) return;
    int n = t >> 4;              // output channel 0..127
    int kg = t & 15;             // k group of 8
    uint32_t sw = swz(n, kg);
#pragma unroll
    for (int m = 0; m < 4; m++) {
        const float* src = (m < 2 ? w1 : w2) + (size_t)n * 256 + (m & 1) * 128 + kg * 8;
        float hf[8], lf[8];
#pragma unroll
        for (int j = 0; j < 8; j++) {
            float v = src[j];
            __nv_bfloat16 h = __float2bfloat16_rn(v);
            hf[j] = __bfloat162float(h);
            lf[j] = v - hf[j];
        }
        uint4 uh, ul;
        uh.x = pack_bf16(hf[0], hf[1]); uh.y = pack_bf16(hf[2], hf[3]);
        uh.z = pack_bf16(hf[4], hf[5]); uh.w = pack_bf16(hf[6], hf[7]);
        ul.x = pack_bf16(lf[0], lf[1]); ul.y = pack_bf16(lf[2], lf[3]);
        ul.z = pack_bf16(lf[4], lf[5]); ul.w = pack_bf16(lf[6], lf[7]);
        *(uint4*)((char*)g_wblob[m * 2 + 0] + sw) = uh;
        *(uint4*)((char*)g_wblob[m * 2 + 1] + sw) = ul;
    }
}

__global__ void count_kernel(const int* __restrict__ col, int E) {
    int e = blockIdx.x * 256 + threadIdx.x;
    if (e < E) atomicAdd(&g_cnt[col[e]], 1.f);
}

// ---------------- mma.sync GEMM ----------------
// MODE 0: g_xa  = x @ w1a^T
// MODE 1: g_h   = ea @ w1b^T + g_xa[row[m]] + b1   (+ fused BN1 stats)
// MODE 2: g_pre = x @ w2a^T + (agg/cnt) @ w2b^T + b2 (+ fused BN2 stats)
// smem: AH 0 / AL 32K / BH 64K / BL 96K (bf16 128x128 each), stats 128K
template <int MODE>
__global__ void __launch_bounds__(256) mm_kernel(
    const float* __restrict__ A, const float* __restrict__ bias,
    const int* __restrict__ rowidx, int M)
{
    extern __shared__ __align__(16) char sm[];
    constexpr int AH = 0, AL = 32768, BH = 65536, BL = 98304;
    constexpr int KT = (MODE == 2) ? 2 : 1;
    constexpr int BB = (MODE == 0) ? 0 : (MODE == 1) ? 2 : 4;

    float* ss = (float*)(sm + 131072);
    float* qq = ss + 128;

    const int tid = threadIdx.x;
    const int lane = tid & 31, wid = tid >> 5;
    const int wm = wid & 3, wn = wid >> 2;
    const int mbase = blockIdx.x * 128;

    float* Outp = (MODE == 0) ? g_xa : (MODE == 1) ? g_h : g_pre;
    float* Sg = (MODE == 1) ? g_s1 : g_s2;
    float* Qg = (MODE == 1) ? g_q1 : g_q2;

    if (MODE != 0 && tid < 128) { ss[tid] = 0.f; qq[tid] = 0.f; }

    const uint32_t sb = smem_u32(sm);
    // per-lane ldmatrix bases
    const uint32_t rx = lane & 7;
    const uint32_t rbA = (uint32_t)(wm * 32 + (lane & 15)) << 8;  // + mi*16*256
    const uint32_t kgoA = lane >> 4;
    uint32_t rbB[4];
#pragma unroll
    for (int nf2 = 0; nf2 < 4; nf2++)
        rbB[nf2] = (uint32_t)(wn * 64 + nf2 * 16 + ((lane >> 4) << 3) + (lane & 7)) << 8;
    const uint32_t kgoB = (lane >> 3) & 1;

    float acc[2][8][4];
#pragma unroll
    for (int mi = 0; mi < 2; mi++)
#pragma unroll
        for (int nf = 0; nf < 8; nf++)
#pragma unroll
            for (int c = 0; c < 4; c++) acc[mi][nf][c] = 0.f;

    for (int kt = 0; kt < KT; kt++) {
        if (kt) __syncthreads();
        // stage B (pre-swizzled blobs)
        {
            const uint4* bh = (const uint4*)g_wblob[BB + kt * 2 + 0];
            const uint4* bl = (const uint4*)g_wblob[BB + kt * 2 + 1];
            for (int i = tid; i < 2048; i += 256) {
                ((uint4*)(sm + BH))[i] = bh[i];
                ((uint4*)(sm + BL))[i] = bl[i];
            }
        }
        // stage + split A
        {
            const float* Ap = (MODE == 2 && kt == 1) ? (const float*)g_agg : A;
#pragma unroll
            for (int it = 0; it < 8; it++) {
                int gi = it * 256 + tid;
                int r = gi >> 4, kg = gi & 15;
                int m = mbase + r; if (m >= M) m = M - 1;
                const float* src = Ap + (size_t)m * C + kg * 8;
                float4 va = *(const float4*)src;
                float4 vb = *(const float4*)(src + 4);
                float v[8] = {va.x, va.y, va.z, va.w, vb.x, vb.y, vb.z, vb.w};
                if (MODE == 2 && kt == 1) {
                    float s = __frcp_rn(fmaxf(g_cnt[m], 1.f));
#pragma unroll
                    for (int j = 0; j < 8; j++) v[j] *= s;
                }
                float hf[8], lf[8];
#pragma unroll
                for (int j = 0; j < 8; j++) {
                    __nv_bfloat16 h = __float2bfloat16_rn(v[j]);
                    hf[j] = __bfloat162float(h);
                    lf[j] = v[j] - hf[j];
                }
                uint4 uh, ul;
                uh.x = pack_bf16(hf[0], hf[1]); uh.y = pack_bf16(hf[2], hf[3]);
                uh.z = pack_bf16(hf[4], hf[5]); uh.w = pack_bf16(hf[6], hf[7]);
                ul.x = pack_bf16(lf[0], lf[1]); ul.y = pack_bf16(lf[2], lf[3]);
                ul.z = pack_bf16(lf[4], lf[5]); ul.w = pack_bf16(lf[6], lf[7]);
                uint32_t sw = swz(r, kg);
                *(uint4*)(sm + AH + sw) = uh;
                *(uint4*)(sm + AL + sw) = ul;
            }
        }
        __syncthreads();

        // mainloop: 8 k16 steps
#pragma unroll
        for (int ks = 0; ks < 8; ks++) {
            uint32_t offA = ((2 * ks + kgoA) ^ rx) << 4;
            uint32_t offB = ((2 * ks + kgoB) ^ rx) << 4;
            uint32_t ah[2][4], al[2][4], bh[4][4], bl[4][4];
            ldsm4(ah[0], sb + AH + rbA + offA);
            ldsm4(ah[1], sb + AH + rbA + (16 << 8) + offA);
            ldsm4(al[0], sb + AL + rbA + offA);
            ldsm4(al[1], sb + AL + rbA + (16 << 8) + offA);
#pragma unroll
            for (int nf2 = 0; nf2 < 4; nf2++) {
                ldsm4(bh[nf2], sb + BH + rbB[nf2] + offB);
                ldsm4(bl[nf2], sb + BL + rbB[nf2] + offB);
            }
#pragma unroll
            for (int mi = 0; mi < 2; mi++)
#pragma unroll
                for (int nf = 0; nf < 8; nf++) {
                    const uint32_t* fh = &bh[nf >> 1][(nf & 1) * 2];
                    const uint32_t* fl = &bl[nf >> 1][(nf & 1) * 2];
                    mma16816(acc[mi][nf], ah[mi], fh);   // hi*hi
                    mma16816(acc[mi][nf], al[mi], fh);   // lo*hi
                    mma16816(acc[mi][nf], ah[mi], fl);   // hi*lo
                }
        }
    }

    // ---------------- epilogue ----------------
    const int g = lane >> 2, np = (lane & 3) * 2;
    float bi0[8], bi1[8];
    if (MODE != 0) {
#pragma unroll
        for (int nf = 0; nf < 8; nf++) {
            int col = wn * 64 + nf * 8 + np;
            bi0[nf] = bias[col]; bi1[nf] = bias[col + 1];
        }
    }
    float s0[8], s1[8], q0[8], q1[8];
#pragma unroll
    for (int nf = 0; nf < 8; nf++) { s0[nf] = s1[nf] = q0[nf] = q1[nf] = 0.f; }

#pragma unroll
    for (int mi = 0; mi < 2; mi++) {
#pragma unroll
        for (int h = 0; h < 2; h++) {
            int r = wm * 32 + mi * 16 + h * 8 + g;
            int m = mbase + r;
            bool valid = (m < M);
            const float* xr = nullptr;
            if (MODE == 1 && valid) xr = g_xa + (size_t)rowidx[m] * C;
            float* orow = Outp + (size_t)m * C;
#pragma unroll
            for (int nf = 0; nf < 8; nf++) {
                int col = wn * 64 + nf * 8 + np;
                float o0 = acc[mi][nf][h * 2 + 0];
                float o1 = acc[mi][nf][h * 2 + 1];
                if (MODE == 1 && valid) {
                    float2 xv = *(const float2*)(xr + col);
                    o0 += xv.x + bi0[nf]; o1 += xv.y + bi1[nf];
                } else if (MODE == 2) {
                    o0 += bi0[nf]; o1 += bi1[nf];
                }
                if (valid) {
                    *(float2*)(orow + col) = make_float2(o0, o1);
                    if (MODE != 0) {
                        s0[nf] += o0; q0[nf] += o0 * o0;
                        s1[nf] += o1; q1[nf] += o1 * o1;
                    }
                }
            }
        }
    }

    if (MODE != 0) {
#pragma unroll
        for (int nf = 0; nf < 8; nf++) {
#pragma unroll
            for (int off = 4; off <= 16; off <<= 1) {
                s0[nf] += __shfl_xor_sync(0xffffffffu, s0[nf], off);
                s1[nf] += __shfl_xor_sync(0xffffffffu, s1[nf], off);
                q0[nf] += __shfl_xor_sync(0xffffffffu, q0[nf], off);
                q1[nf] += __shfl_xor_sync(0xffffffffu, q1[nf], off);
            }
        }
        if (lane < 4) {
#pragma unroll
            for (int nf = 0; nf < 8; nf++) {
                int col = wn * 64 + nf * 8 + lane * 2;
                atomicAdd(&ss[col], s0[nf]); atomicAdd(&ss[col + 1], s1[nf]);
                atomicAdd(&qq[col], q0[nf]); atomicAdd(&qq[col + 1], q1[nf]);
            }
        }
        __syncthreads();
        if (tid < 128) {
            atomicAdd(&Sg[tid], ss[tid]);
            atomicAdd(&Qg[tid], qq[tid]);
        }
    }
}

// ---------------- BN coefficient finalize ----------------
__global__ void finalize_kernel(int sel, const float* __restrict__ bnw,
                                const float* __restrict__ bnb, float minv) {
    int j = threadIdx.x;
    float s  = sel ? g_s2[j] : g_s1[j];
    float q  = sel ? g_q2[j] : g_q1[j];
    float mu = s * minv;
    float var = q * minv - mu * mu;
    float r = rsqrtf(var + BN_EPS);
    float a = r * bnw[j];
    float c = bnb[j] - mu * a;
    if (sel) { g_a2[j] = a; g_c2[j] = c; }
    else     { g_a1[j] = a; g_c1[j] = c; }
}

// ---------------- BN1 + ELU + vectorized scatter-add ----------------
__global__ void scatter_kernel(const int* __restrict__ col, int E) {
    int g = blockIdx.x * 256 + threadIdx.x;
    if (g >= E * 32) return;
    int e = g >> 5;
    int cq = (g & 31) * 4;
    float4 v = *(const float4*)(g_h + (size_t)g * 4);
    float4 a = *(const float4*)(g_a1 + cq);
    float4 c = *(const float4*)(g_c1 + cq);
    int d = col[e];
    float* base = g_agg + (size_t)d * C + cq;
    red4(base,
         eluf(fmaf(v.x, a.x, c.x)),
         eluf(fmaf(v.y, a.y, c.y)),
         eluf(fmaf(v.z, a.z, c.z)),
         eluf(fmaf(v.w, a.w, c.w)));
}

// ---------------- BN2 + ELU -> output ----------------
__global__ void final_kernel(float* __restrict__ out, int n) {
    int g = blockIdx.x * 256 + threadIdx.x;
    if (g >= n * 32) return;
    int cq = (g & 31) * 4;
    float4 v = *(const float4*)(g_pre + (size_t)g * 4);
    float4 a = *(const float4*)(g_a2 + cq);
    float4 c = *(const float4*)(g_c2 + cq);
    float4 o;
    o.x = eluf(fmaf(v.x, a.x, c.x));
    o.y = eluf(fmaf(v.y, a.y, c.y));
    o.z = eluf(fmaf(v.z, a.z, c.z));
    o.w = eluf(fmaf(v.w, a.w, c.w));
    *(float4*)(out + (size_t)g * 4) = o;
}

// ---------------- launch ----------------
extern "C" void kernel_launch(void* const* d_in, const int* in_sizes, int n_in,
                              void* d_out, int out_size) {
    const float* x    = (const float*)d_in[0];
    const int*   ei   = (const int*)d_in[1];
    const float* ea   = (const float*)d_in[2];
    const float* w1   = (const float*)d_in[5];
    const float* b1   = (const float*)d_in[6];
    const float* bn1w = (const float*)d_in[7];
    const float* bn1b = (const float*)d_in[8];
    const float* w2   = (const float*)d_in[9];
    const float* b2   = (const float*)d_in[10];
    const float* bn2w = (const float*)d_in[11];
    const float* bn2b = (const float*)d_in[12];
    float* out = (float*)d_out;

    int n = in_sizes[0] / C;           // 50000
    int E = in_sizes[2] / C;           // 800000
    const int* row = ei;
    const int* col = ei + E;

    const int SMEM = 131072 + 1024;
    cudaFuncSetAttribute(mm_kernel<0>, cudaFuncAttributeMaxDynamicSharedMemorySize, SMEM);
    cudaFuncSetAttribute(mm_kernel<1>, cudaFuncAttributeMaxDynamicSharedMemorySize, SMEM);
    cudaFuncSetAttribute(mm_kernel<2>, cudaFuncAttributeMaxDynamicSharedMemorySize, SMEM);

    zero_kernel<<<(NN_MAX * C / 4 + 255) / 256, 256>>>();
    prep_w<<<8, 256>>>(w1, w2);
    count_kernel<<<(E + 255) / 256, 256>>>(col, E);

    int ntile = (n + 127) / 128;
    int etile = (E + 127) / 128;

    // xa = x @ w1a^T
    mm_kernel<0><<<ntile, 256, SMEM>>>(x, nullptr, nullptr, n);
    // h = ea @ w1b^T + xa[row] + b1  (stats fused)
    mm_kernel<1><<<etile, 256, SMEM>>>(ea, b1, row, E);
    finalize_kernel<<<1, C>>>(0, bn1w, bn1b, 1.f / (float)E);

    scatter_kernel<<<(E * 32 + 255) / 256, 256>>>(col, E);

    // pre = [x, agg/cnt] @ w2^T + b2  (stats fused)
    mm_kernel<2><<<ntile, 256, SMEM>>>(x, b2, nullptr, n);
    finalize_kernel<<<1, C>>>(1, bn2w, bn2b, 1.f / (float)n);

    final_kernel<<<(n * 32 + 255) / 256, 256>>>(out, n);
}

// round 5
// speedup vs baseline: 2.1811x; 1.6115x over previous
#include <cuda_runtime.h>
#include <cuda_bf16.h>
#include <math.h>
#include <stdint.h>

#define C 128
#define NE_MAX 800000
#define NN_MAX 50000
#define BN_EPS 1e-5f

// ---------------- scratch (device globals; no runtime alloc) ----------------
__device__ float g_h[(size_t)NE_MAX * C];     // edge MLP pre-BN output
__device__ float g_xa[(size_t)NN_MAX * C];    // x @ w1a^T
__device__ float g_agg[(size_t)NN_MAX * C];   // scatter sum
__device__ float g_pre[(size_t)NN_MAX * C];   // node MLP pre-BN output
__device__ float g_cnt[NN_MAX];
__device__ float g_s1[C], g_q1[C], g_s2[C], g_q2[C];
__device__ float g_a1[C], g_c1[C], g_a2[C], g_c2[C];
// bf16 weight blobs in smem-swizzled [n][k] layout:
// 0,1 = w1a hi/lo ; 2,3 = w1b hi/lo ; 4,5 = w2a hi/lo ; 6,7 = w2b hi/lo
__device__ __align__(16) uint16_t g_wblob[8][128 * 128];

// ---------------- helpers ----------------
__device__ __forceinline__ uint32_t smem_u32(const void* p) {
    return (uint32_t)__cvta_generic_to_shared(p);
}
__device__ __forceinline__ void ldsm4(uint32_t* r, uint32_t addr) {
    asm volatile("ldmatrix.sync.aligned.m8n8.x4.shared.b16 {%0,%1,%2,%3}, [%4];"
                 : "=r"(r[0]), "=r"(r[1]), "=r"(r[2]), "=r"(r[3]) : "r"(addr));
}
__device__ __forceinline__ void mma16816(float* c, const uint32_t* a, const uint32_t* b) {
    asm volatile(
        "mma.sync.aligned.m16n8k16.row.col.f32.bf16.bf16.f32 "
        "{%0,%1,%2,%3}, {%4,%5,%6,%7}, {%8,%9}, {%0,%1,%2,%3};"
        : "+f"(c[0]), "+f"(c[1]), "+f"(c[2]), "+f"(c[3])
        : "r"(a[0]), "r"(a[1]), "r"(a[2]), "r"(a[3]), "r"(b[0]), "r"(b[1]));
}
__device__ __forceinline__ unsigned pack_bf16(float lo, float hi) {
    __nv_bfloat162 p = __floats2bfloat162_rn(lo, hi);
    return *reinterpret_cast<unsigned*>(&p);
}
__device__ __forceinline__ float eluf(float v) { return v > 0.f ? v : expm1f(v); }
__device__ __forceinline__ void red4(float* p, float a, float b, float c, float d) {
    asm volatile("red.global.add.v4.f32 [%0], {%1,%2,%3,%4};"
                 :: "l"(p), "f"(a), "f"(b), "f"(c), "f"(d) : "memory");
}
// swizzled byte offset for (row, 16B k-group) within a [rows]x128 bf16 tile
__device__ __forceinline__ uint32_t swz(int row, int kg) {
    return ((uint32_t)row << 8) + (((uint32_t)(kg ^ (row & 7))) << 4);
}

// ---------------- small kernels ----------------
__global__ void zero_kernel() {
    int g = blockIdx.x * 256 + threadIdx.x;
    if (g < NN_MAX * C / 4) ((float4*)g_agg)[g] = make_float4(0.f, 0.f, 0.f, 0.f);
    if (g < NN_MAX) g_cnt[g] = 0.f;
    if (g < C) { g_s1[g] = 0.f; g_q1[g] = 0.f; g_s2[g] = 0.f; g_q2[g] = 0.f; }
}

// split w1/w2 into hi/lo bf16 blobs, swizzled [n][k]
__global__ void prep_w(const float* __restrict__ w1, const float* __restrict__ w2) {
    int t = blockIdx.x * 256 + threadIdx.x;   // 0..2047
    if (t >= 2048) return;
    int n = t >> 4;              // output channel 0..127
    int kg = t & 15;             // k group of 8
    uint32_t sw = swz(n, kg);
#pragma unroll
    for (int m = 0; m < 4; m++) {
        const float* src = (m < 2 ? w1 : w2) + (size_t)n * 256 + (m & 1) * 128 + kg * 8;
        float hf[8], lf[8];
#pragma unroll
        for (int j = 0; j < 8; j++) {
            float v = src[j];
            __nv_bfloat16 h = __float2bfloat16_rn(v);
            hf[j] = __bfloat162float(h);
            lf[j] = v - hf[j];
        }
        uint4 uh, ul;
        uh.x = pack_bf16(hf[0], hf[1]); uh.y = pack_bf16(hf[2], hf[3]);
        uh.z = pack_bf16(hf[4], hf[5]); uh.w = pack_bf16(hf[6], hf[7]);
        ul.x = pack_bf16(lf[0], lf[1]); ul.y = pack_bf16(lf[2], lf[3]);
        ul.z = pack_bf16(lf[4], lf[5]); ul.w = pack_bf16(lf[6], lf[7]);
        *(uint4*)((char*)g_wblob[m * 2 + 0] + sw) = uh;
        *(uint4*)((char*)g_wblob[m * 2 + 1] + sw) = ul;
    }
}

__global__ void count_kernel(const int* __restrict__ col, int E) {
    int e = blockIdx.x * 256 + threadIdx.x;
    if (e < E) atomicAdd(&g_cnt[col[e]], 1.f);
}

// ---------------- persistent mma.sync GEMM (BM=64, B resident) ----------------
// MODE 0: g_xa  = x @ w1a^T
// MODE 1: g_h   = ea @ w1b^T + g_xa[row[m]] + b1    (+ fused BN1 stats)
// MODE 2: g_pre = x @ w2a^T
// MODE 3: g_pre += (agg/cnt) @ w2b^T + b2           (+ fused BN2 stats)
// smem: BH 0 (32K) / BL 32K / AH 64K (16K) / AL 80K  -> 96 KB, 2 CTAs/SM
template <int MODE>
__global__ void __launch_bounds__(256, 2) mm_kernel(
    const float* __restrict__ A, const float* __restrict__ bias,
    const int* __restrict__ rowidx, int M)
{
    extern __shared__ __align__(16) char sm[];
    constexpr int BH = 0, BL = 32768, AH = 65536, AL = 81920;
    constexpr int BB = (MODE == 0) ? 0 : (MODE == 1) ? 2 : (MODE == 2) ? 4 : 6;
    constexpr bool STATS = (MODE == 1) || (MODE == 3);

    const int tid = threadIdx.x;
    const int lane = tid & 31, wid = tid >> 5;
    const int wm = wid >> 2;          // 0..1 : 32-row group
    const int wn = wid & 3;           // 0..3 : 32-col group

    float* Outp = (MODE == 0) ? g_xa : (MODE == 1) ? g_h : g_pre;
    float* Sg = (MODE == 1) ? g_s1 : g_s2;
    float* Qg = (MODE == 1) ? g_q1 : g_q2;
    const float* Ap = (MODE == 3) ? (const float*)g_agg : A;

    // ---- stage B once (pre-swizzled, L2-resident) ----
    {
        const uint4* bh = (const uint4*)g_wblob[BB + 0];
        const uint4* bl = (const uint4*)g_wblob[BB + 1];
        for (int i = tid; i < 2048; i += 256) {
            ((uint4*)(sm + BH))[i] = bh[i];
            ((uint4*)(sm + BL))[i] = bl[i];
        }
    }

    const uint32_t sb = smem_u32(sm);
    const uint32_t rx = lane & 7;
    const uint32_t rbA = (uint32_t)(wm * 32 + (lane & 15)) << 8;
    const uint32_t kgoA = lane >> 4;
    uint32_t rbB[2];
#pragma unroll
    for (int nf2 = 0; nf2 < 2; nf2++)
        rbB[nf2] = (uint32_t)(wn * 32 + nf2 * 16 + ((lane >> 4) << 3) + (lane & 7)) << 8;
    const uint32_t kgoB = (lane >> 3) & 1;

    // bias (constant across tiles)
    const int np = (lane & 3) * 2;
    float bi0[4], bi1[4];
    if (MODE == 1 || MODE == 3) {
#pragma unroll
        for (int nf = 0; nf < 4; nf++) {
            int col = wn * 32 + nf * 8 + np;
            bi0[nf] = bias[col]; bi1[nf] = bias[col + 1];
        }
    }
    // register BN stats accumulated across tiles
    float s0[4], s1[4], q0[4], q1[4];
#pragma unroll
    for (int nf = 0; nf < 4; nf++) { s0[nf] = s1[nf] = q0[nf] = q1[nf] = 0.f; }

    const int tiles = (M + 63) >> 6;
    for (int t = blockIdx.x; t < tiles; t += gridDim.x) {
        const int mbase = t * 64;
        __syncthreads();   // previous tile's ldsm done before overwriting A
        // ---- stage + split A tile (64 x 128) ----
#pragma unroll
        for (int it = 0; it < 4; it++) {
            int gi = it * 256 + tid;        // 0..1023
            int r = gi >> 4, kg = gi & 15;
            int m = mbase + r; if (m >= M) m = M - 1;
            const float* src = Ap + (size_t)m * C + kg * 8;
            float4 va = *(const float4*)src;
            float4 vb = *(const float4*)(src + 4);
            float v[8] = {va.x, va.y, va.z, va.w, vb.x, vb.y, vb.z, vb.w};
            if (MODE == 3) {
                float s = __frcp_rn(fmaxf(g_cnt[m], 1.f));
#pragma unroll
                for (int j = 0; j < 8; j++) v[j] *= s;
            }
            float hf[8], lf[8];
#pragma unroll
            for (int j = 0; j < 8; j++) {
                __nv_bfloat16 h = __float2bfloat16_rn(v[j]);
                hf[j] = __bfloat162float(h);
                lf[j] = v[j] - hf[j];
            }
            uint4 uh, ul;
            uh.x = pack_bf16(hf[0], hf[1]); uh.y = pack_bf16(hf[2], hf[3]);
            uh.z = pack_bf16(hf[4], hf[5]); uh.w = pack_bf16(hf[6], hf[7]);
            ul.x = pack_bf16(lf[0], lf[1]); ul.y = pack_bf16(lf[2], lf[3]);
            ul.z = pack_bf16(lf[4], lf[5]); ul.w = pack_bf16(lf[6], lf[7]);
            uint32_t sw = swz(r, kg);
            *(uint4*)(sm + AH + sw) = uh;
            *(uint4*)(sm + AL + sw) = ul;
        }
        __syncthreads();

        // ---- MMA mainloop: 8 k16 steps ----
        float acc[2][4][4];
#pragma unroll
        for (int mi = 0; mi < 2; mi++)
#pragma unroll
            for (int nf = 0; nf < 4; nf++)
#pragma unroll
                for (int cc = 0; cc < 4; cc++) acc[mi][nf][cc] = 0.f;

#pragma unroll
        for (int ks = 0; ks < 8; ks++) {
            uint32_t offA = ((2 * ks + kgoA) ^ rx) << 4;
            uint32_t offB = ((2 * ks + kgoB) ^ rx) << 4;
            uint32_t ah[2][4], al[2][4], bh[2][4], bl[2][4];
            ldsm4(ah[0], sb + AH + rbA + offA);
            ldsm4(ah[1], sb + AH + rbA + (16 << 8) + offA);
            ldsm4(al[0], sb + AL + rbA + offA);
            ldsm4(al[1], sb + AL + rbA + (16 << 8) + offA);
#pragma unroll
            for (int nf2 = 0; nf2 < 2; nf2++) {
                ldsm4(bh[nf2], sb + BH + rbB[nf2] + offB);
                ldsm4(bl[nf2], sb + BL + rbB[nf2] + offB);
            }
#pragma unroll
            for (int mi = 0; mi < 2; mi++)
#pragma unroll
                for (int nf = 0; nf < 4; nf++) {
                    const uint32_t* fh = &bh[nf >> 1][(nf & 1) * 2];
                    const uint32_t* fl = &bl[nf >> 1][(nf & 1) * 2];
                    mma16816(acc[mi][nf], ah[mi], fh);   // hi*hi
                    mma16816(acc[mi][nf], al[mi], fh);   // lo*hi
                    mma16816(acc[mi][nf], ah[mi], fl);   // hi*lo
                }
        }

        // ---- epilogue ----
        const int g = lane >> 2;
#pragma unroll
        for (int mi = 0; mi < 2; mi++) {
#pragma unroll
            for (int h = 0; h < 2; h++) {
                int r = wm * 32 + mi * 16 + h * 8 + g;
                int m = mbase + r;
                bool valid = (m < M);
                const float* xr = nullptr;
                if (MODE == 1 && valid) xr = g_xa + (size_t)rowidx[m] * C;
                float* orow = Outp + (size_t)m * C;
#pragma unroll
                for (int nf = 0; nf < 4; nf++) {
                    int col = wn * 32 + nf * 8 + np;
                    float o0 = acc[mi][nf][h * 2 + 0];
                    float o1 = acc[mi][nf][h * 2 + 1];
                    if (MODE == 1 && valid) {
                        float2 xv = *(const float2*)(xr + col);
                        o0 += xv.x + bi0[nf]; o1 += xv.y + bi1[nf];
                    } else if (MODE == 3 && valid) {
                        float2 pv = *(const float2*)(orow + col);
                        o0 += pv.x + bi0[nf]; o1 += pv.y + bi1[nf];
                    }
                    if (valid) {
                        *(float2*)(orow + col) = make_float2(o0, o1);
                        if (STATS) {
                            s0[nf] += o0; q0[nf] += o0 * o0;
                            s1[nf] += o1; q1[nf] += o1 * o1;
                        }
                    }
                }
            }
        }
    }

    // ---- flush BN stats once per warp ----
    if (STATS) {
#pragma unroll
        for (int nf = 0; nf < 4; nf++) {
#pragma unroll
            for (int off = 4; off <= 16; off <<= 1) {
                s0[nf] += __shfl_xor_sync(0xffffffffu, s0[nf], off);
                s1[nf] += __shfl_xor_sync(0xffffffffu, s1[nf], off);
                q0[nf] += __shfl_xor_sync(0xffffffffu, q0[nf], off);
                q1[nf] += __shfl_xor_sync(0xffffffffu, q1[nf], off);
            }
        }
        if (lane < 4) {
#pragma unroll
            for (int nf = 0; nf < 4; nf++) {
                int col = wn * 32 + nf * 8 + lane * 2;
                atomicAdd(&Sg[col], s0[nf]); atomicAdd(&Sg[col + 1], s1[nf]);
                atomicAdd(&Qg[col], q0[nf]); atomicAdd(&Qg[col + 1], q1[nf]);
            }
        }
    }
}

// ---------------- BN coefficient finalize ----------------
__global__ void finalize_kernel(int sel, const float* __restrict__ bnw,
                                const float* __restrict__ bnb, float minv) {
    int j = threadIdx.x;
    float s  = sel ? g_s2[j] : g_s1[j];
    float q  = sel ? g_q2[j] : g_q1[j];
    float mu = s * minv;
    float var = q * minv - mu * mu;
    float r = rsqrtf(var + BN_EPS);
    float a = r * bnw[j];
    float c = bnb[j] - mu * a;
    if (sel) { g_a2[j] = a; g_c2[j] = c; }
    else     { g_a1[j] = a; g_c1[j] = c; }
}

// ---------------- BN1 + ELU + vectorized scatter-add ----------------
__global__ void scatter_kernel(const int* __restrict__ col, int E) {
    int g = blockIdx.x * 256 + threadIdx.x;
    if (g >= E * 32) return;
    int e = g >> 5;
    int cq = (g & 31) * 4;
    float4 v = *(const float4*)(g_h + (size_t)g * 4);
    float4 a = *(const float4*)(g_a1 + cq);
    float4 c = *(const float4*)(g_c1 + cq);
    int d = col[e];
    float* base = g_agg + (size_t)d * C + cq;
    red4(base,
         eluf(fmaf(v.x, a.x, c.x)),
         eluf(fmaf(v.y, a.y, c.y)),
         eluf(fmaf(v.z, a.z, c.z)),
         eluf(fmaf(v.w, a.w, c.w)));
}

// ---------------- BN2 + ELU -> output ----------------
__global__ void final_kernel(float* __restrict__ out, int n) {
    int g = blockIdx.x * 256 + threadIdx.x;
    if (g >= n * 32) return;
    int cq = (g & 31) * 4;
    float4 v = *(const float4*)(g_pre + (size_t)g * 4);
    float4 a = *(const float4*)(g_a2 + cq);
    float4 c = *(const float4*)(g_c2 + cq);
    float4 o;
    o.x = eluf(fmaf(v.x, a.x, c.x));
    o.y = eluf(fmaf(v.y, a.y, c.y));
    o.z = eluf(fmaf(v.z, a.z, c.z));
    o.w = eluf(fmaf(v.w, a.w, c.w));
    *(float4*)(out + (size_t)g * 4) = o;
}

// ---------------- launch ----------------
extern "C" void kernel_launch(void* const* d_in, const int* in_sizes, int n_in,
                              void* d_out, int out_size) {
    const float* x    = (const float*)d_in[0];
    const int*   ei   = (const int*)d_in[1];
    const float* ea   = (const float*)d_in[2];
    const float* w1   = (const float*)d_in[5];
    const float* b1   = (const float*)d_in[6];
    const float* bn1w = (const float*)d_in[7];
    const float* bn1b = (const float*)d_in[8];
    const float* w2   = (const float*)d_in[9];
    const float* b2   = (const float*)d_in[10];
    const float* bn2w = (const float*)d_in[11];
    const float* bn2b = (const float*)d_in[12];
    float* out = (float*)d_out;

    int n = in_sizes[0] / C;           // 50000
    int E = in_sizes[2] / C;           // 800000
    const int* row = ei;
    const int* col = ei + E;

    const int SMEM = 98304;            // 96 KB -> 2 CTAs/SM
    cudaFuncSetAttribute(mm_kernel<0>, cudaFuncAttributeMaxDynamicSharedMemorySize, SMEM);
    cudaFuncSetAttribute(mm_kernel<1>, cudaFuncAttributeMaxDynamicSharedMemorySize, SMEM);
    cudaFuncSetAttribute(mm_kernel<2>, cudaFuncAttributeMaxDynamicSharedMemorySize, SMEM);
    cudaFuncSetAttribute(mm_kernel<3>, cudaFuncAttributeMaxDynamicSharedMemorySize, SMEM);

    zero_kernel<<<(NN_MAX * C / 4 + 255) / 256, 256>>>();
    prep_w<<<8, 256>>>(w1, w2);
    count_kernel<<<(E + 255) / 256, 256>>>(col, E);

    const int GRID = 296;              // 2 persistent CTAs per SM
    int ngrid = min(GRID, (n + 63) / 64);
    int egrid = min(GRID, (E + 63) / 64);

    // xa = x @ w1a^T
    mm_kernel<0><<<ngrid, 256, SMEM>>>(x, nullptr, nullptr, n);
    // h = ea @ w1b^T + xa[row] + b1  (stats fused)
    mm_kernel<1><<<egrid, 256, SMEM>>>(ea, b1, row, E);
    finalize_kernel<<<1, C>>>(0, bn1w, bn1b, 1.f / (float)E);

    scatter_kernel<<<(E * 32 + 255) / 256, 256>>>(col, E);

    // pre = x @ w2a^T ; pre += (agg/cnt) @ w2b^T + b2 (stats fused)
    mm_kernel<2><<<ngrid, 256, SMEM>>>(x, nullptr, nullptr, n);
    mm_kernel<3><<<ngrid, 256, SMEM>>>(x, b2, nullptr, n);
    finalize_kernel<<<1, C>>>(1, bn2w, bn2b, 1.f / (float)n);

    final_kernel<<<(n * 32 + 255) / 256, 256>>>(out, n);
}